// round 9
// baseline (speedup 1.0000x reference)
#include <cuda_runtime.h>
#include <math.h>
#include <stdint.h>

#define Bz 4
#define T 2048
#define C 1024
#define NH 16
#define HS 64
#define M (Bz*T)

#define ASTRIDE 36
#define BSTRIDE 136
#define STAGE_FLOATS (4608 + 4352)   // A 128x36 + B 32x136

// Scratch (allocation-free rule: __device__ globals)
__device__ float g_q[Bz*NH*T*HS];   // [B,NH,T,HS] fp32
__device__ float g_k[Bz*NH*T*HS];   // [B,NH,T,HS] tf32-rounded
__device__ float g_v[Bz*NH*T*HS];   // [B,NH,HS,T] tf32-rounded, transposed
__device__ float g_att[M*C];        // [B,T,C] tf32-rounded
__device__ float g_x [M*C];         // tf32-rounded X
__device__ float g_wq[C*C];
__device__ float g_wk[C*C];
__device__ float g_wv[C*C];
__device__ float g_wp[C*C];

// ---------------------------------------------------------------------------
__device__ __forceinline__ float f2tf32(float f) {
    uint32_t u;
    asm("cvt.rna.tf32.f32 %0, %1;" : "=r"(u) : "f"(f));
    return __uint_as_float(u);
}

__device__ __forceinline__ void mma_tf32(float4 &d,
    uint32_t a0, uint32_t a1, uint32_t a2, uint32_t a3,
    uint32_t b0, uint32_t b1)
{
    asm volatile(
        "mma.sync.aligned.m16n8k8.row.col.f32.tf32.tf32.f32 "
        "{%0,%1,%2,%3}, {%4,%5,%6,%7}, {%8,%9}, {%0,%1,%2,%3};\n"
        : "+f"(d.x), "+f"(d.y), "+f"(d.z), "+f"(d.w)
        : "r"(a0), "r"(a1), "r"(a2), "r"(a3), "r"(b0), "r"(b1));
}

__device__ __forceinline__ void cp16(float* smem_dst, const float* gsrc) {
    uint32_t s = (uint32_t)__cvta_generic_to_shared(smem_dst);
    asm volatile("cp.async.cg.shared.global [%0], [%1], 16;" :: "r"(s), "l"(gsrc));
}
#define CP_COMMIT()  asm volatile("cp.async.commit_group;" ::: "memory")
#define CP_WAIT(N)   asm volatile("cp.async.wait_group %0;" :: "n"(N) : "memory")

// ---------------------------------------------------------------------------
// merged pre-conversion: X (8192 blocks) + Wq/Wk/Wv/Wp (1024 each)
// ---------------------------------------------------------------------------
__global__ void cvt_all(const float* __restrict__ x,
                        const float* __restrict__ wq, const float* __restrict__ wk,
                        const float* __restrict__ wv, const float* __restrict__ wp)
{
    int b = blockIdx.x;
    const float* s; float* d; int off;
    if (b < 8192)       { s = x;  d = g_x;  off = b; }
    else if (b < 9216)  { s = wq; d = g_wq; off = b - 8192; }
    else if (b < 10240) { s = wk; d = g_wk; off = b - 9216; }
    else if (b < 11264) { s = wv; d = g_wv; off = b - 10240; }
    else                { s = wp; d = g_wp; off = b - 11264; }
    int i = (off * 256 + threadIdx.x) * 4;
    float4 v = *(const float4*)&s[i];
    *(float4*)&d[i] = make_float4(f2tf32(v.x), f2tf32(v.y), f2tf32(v.z), f2tf32(v.w));
}

// ---------------------------------------------------------------------------
// Tensor-core GEMM: 128 threads, 4 warps, warp tile 64x64 (1.0 LDS/MMA),
// block tile 128x128, BK=32, 3-stage cp.async ring.
// ---------------------------------------------------------------------------
template<int QKV>
__global__ __launch_bounds__(128, 2)
void gemm_tc(const float* __restrict__ b0p,
             const float* __restrict__ b1p,
             const float* __restrict__ b2p,
             float* __restrict__ outp)
{
    extern __shared__ float smp[];   // 3 stages x STAGE_FLOATS

    const float* X;
    const float* W;
    const float* bias;
    float* out;
    int sel, tileN;
    if (QKV) {
        X = g_x;
        sel = blockIdx.x >> 3;
        tileN = (blockIdx.x & 7) * 128;
        W    = (sel == 0) ? g_wq : (sel == 1) ? g_wk : g_wv;
        bias = (sel == 0) ? b0p  : (sel == 1) ? b1p  : b2p;
        out  = (sel == 0) ? g_q  : (sel == 1) ? g_k  : g_v;
    } else {
        X = g_att;
        sel = 3;
        tileN = blockIdx.x * 128;
        W = g_wp; bias = b0p; out = outp;
    }

    const int tid   = threadIdx.x;
    const int lane  = tid & 31;
    const int warp  = tid >> 5;      // 0..3
    const int warpM = warp >> 1;     // 0..1
    const int warpN = warp & 1;      // 0..1
    const int g     = lane >> 2;
    const int t     = lane & 3;

    const int tileM = blockIdx.y * 128;

    const int am = tid >> 3;          // 0..15, +16*i
    const int ac = (tid & 7) * 4;
    const int bk = tid >> 5;          // 0..3,  +4*i
    const int bc = (tid & 31) * 4;

    float4 acc[4][8];
    #pragma unroll
    for (int i = 0; i < 4; i++)
        #pragma unroll
        for (int j = 0; j < 8; j++)
            acc[i][j] = make_float4(0.f, 0.f, 0.f, 0.f);

    auto pref = [&](int s, int k0) {
        float* As = smp + s * STAGE_FLOATS;
        float* Bs = As + 4608;
        #pragma unroll
        for (int i = 0; i < 8; i++) {
            cp16(&As[(am + 16 * i) * ASTRIDE + ac],
                 &X[(size_t)(tileM + am + 16 * i) * C + k0 + ac]);
            cp16(&Bs[(bk + 4 * i) * BSTRIDE + bc],
                 &W[(size_t)(k0 + bk + 4 * i) * C + tileN + bc]);
        }
    };

    pref(0, 0);  CP_COMMIT();
    pref(1, 32); CP_COMMIT();

    for (int it = 0; it < 32; it++) {
        if (it < 31) { CP_WAIT(1); } else { CP_WAIT(0); }
        __syncthreads();
        if (it + 2 < 32) { pref((it + 2) % 3, (it + 2) * 32); CP_COMMIT(); }

        const float* As = smp + (it % 3) * STAGE_FLOATS;
        const float* Bs = As + 4608;

        #pragma unroll
        for (int ks = 0; ks < 4; ks++) {
            uint32_t af[4][4];
            uint32_t bfr[8][2];
            #pragma unroll
            for (int mf = 0; mf < 4; mf++) {
                const int r0 = (warpM * 64 + mf * 16 + g) * ASTRIDE + ks * 8 + t;
                af[mf][0] = __float_as_uint(As[r0]);
                af[mf][1] = __float_as_uint(As[r0 + 8 * ASTRIDE]);
                af[mf][2] = __float_as_uint(As[r0 + 4]);
                af[mf][3] = __float_as_uint(As[r0 + 8 * ASTRIDE + 4]);
            }
            #pragma unroll
            for (int nf = 0; nf < 8; nf++) {
                const int c0 = (ks * 8 + t) * BSTRIDE + warpN * 64 + nf * 8 + g;
                bfr[nf][0] = __float_as_uint(Bs[c0]);
                bfr[nf][1] = __float_as_uint(Bs[c0 + 4 * BSTRIDE]);
            }
            #pragma unroll
            for (int mf = 0; mf < 4; mf++)
                #pragma unroll
                for (int nf = 0; nf < 8; nf++)
                    mma_tf32(acc[mf][nf],
                             af[mf][0], af[mf][1], af[mf][2], af[mf][3],
                             bfr[nf][0], bfr[nf][1]);
        }
    }

    // epilogue
    #pragma unroll
    for (int nf = 0; nf < 8; nf++) {
        const int n0 = tileN + warpN * 64 + nf * 8 + t * 2;
        const float bv0 = bias[n0];
        const float bv1 = bias[n0 + 1];
        float inv = 0.f;
        if (QKV) {
            const int ip = (n0 & 63) >> 1;
            inv = powf(10000.0f, -(float)ip / 32.0f);
        }
        #pragma unroll
        for (int mf = 0; mf < 4; mf++) {
            float4 a = acc[mf][nf];
            const int r0 = tileM + warpM * 64 + mf * 16 + g;
            float x0 = a.x + bv0, x1 = a.y + bv1;
            float y0 = a.z + bv0, y1 = a.w + bv1;
            if (!QKV) {
                *(float2*)&out[(size_t)r0 * C + n0]       = make_float2(x0, x1);
                *(float2*)&out[(size_t)(r0 + 8) * C + n0] = make_float2(y0, y1);
            } else {
                const int bb = r0 / T;
                const int t0 = r0 % T;
                const int h  = n0 >> 6;
                const int d0 = n0 & 63;
                if (sel < 2) {
                    float sn, cs;
                    sincosf((float)t0 * inv, &sn, &cs);
                    float u0 = x0 * cs - x1 * sn;
                    float u1 = x0 * sn + x1 * cs;
                    x0 = u0; x1 = u1;
                    sincosf((float)(t0 + 8) * inv, &sn, &cs);
                    float w0 = y0 * cs - y1 * sn;
                    float w1 = y0 * sn + y1 * cs;
                    y0 = w0; y1 = w1;
                }
                if (sel == 0) {
                    float* dst = out + (((size_t)bb * NH + h) * T + t0) * HS + d0;
                    *(float2*)dst            = make_float2(x0, x1);
                    *(float2*)(dst + 8 * HS) = make_float2(y0, y1);
                } else if (sel == 1) {
                    float* dst = out + (((size_t)bb * NH + h) * T + t0) * HS + d0;
                    *(float2*)dst            = make_float2(f2tf32(x0), f2tf32(x1));
                    *(float2*)(dst + 8 * HS) = make_float2(f2tf32(y0), f2tf32(y1));
                } else {
                    float* dst = out + (((size_t)bb * NH + h) * HS + d0) * T + t0;
                    dst[0]     = f2tf32(x0);
                    dst[T]     = f2tf32(x1);
                    dst[8]     = f2tf32(y0);
                    dst[T + 8] = f2tf32(y1);
                }
            }
        }
    }
}

// ---------------------------------------------------------------------------
// Flash attention: 128 q rows/block, 4 warps, 32 q rows per warp (2 m16 tiles)
// QK 1-term tf32, PV tf32. 3-stage cp.async ring. Fully-masked a-tiles skipped.
// ---------------------------------------------------------------------------
__global__ __launch_bounds__(128, 2)
void attn_tc()
{
    extern __shared__ float smp[];   // 3 x 8704 floats

    const int qt   = gridDim.x - 1 - blockIdx.x;   // big tiles first
    const int h    = blockIdx.y;
    const int bb   = blockIdx.z;
    const int tid  = threadIdx.x;
    const int lane = tid & 31;
    const int warp = tid >> 5;
    const int g    = lane >> 2;
    const int t    = lane & 3;

    const float* kbase = g_k + (size_t)(bb * NH + h) * T * HS;   // [key][dim]
    const float* vbase = g_v + (size_t)(bb * NH + h) * HS * T;   // [dim][key]
    const float* qbase = g_q + ((size_t)(bb * NH + h) * T + (size_t)qt * 128) * HS;

    // two m16 A-tiles per warp: local row base = warp*32 + a*16
    uint32_t qa[2][8][4];
    #pragma unroll
    for (int a = 0; a < 2; a++) {
        const int base = warp * 32 + a * 16;
        #pragma unroll
        for (int ks = 0; ks < 8; ks++) {
            qa[a][ks][0] = __float_as_uint(f2tf32(qbase[(size_t)(base + g)     * HS + ks * 8 + t]     * 0.125f));
            qa[a][ks][1] = __float_as_uint(f2tf32(qbase[(size_t)(base + g + 8) * HS + ks * 8 + t]     * 0.125f));
            qa[a][ks][2] = __float_as_uint(f2tf32(qbase[(size_t)(base + g)     * HS + ks * 8 + t + 4] * 0.125f));
            qa[a][ks][3] = __float_as_uint(f2tf32(qbase[(size_t)(base + g + 8) * HS + ks * 8 + t + 4] * 0.125f));
        }
    }

    auto pref = [&](int s, int kt) {
        float* Kh = smp + s * 8704;
        float* Vv = Kh + 4352;
        #pragma unroll
        for (int i = 0; i < 8; i++) {
            int idx = tid + i * 128;
            int r  = idx >> 4;
            int c4 = (idx & 15) * 4;
            cp16(&Kh[r * 68 + c4], kbase + (size_t)(kt * 64 + r) * HS + c4);
            cp16(&Vv[r * 68 + c4], vbase + (size_t)r * T + kt * 64 + c4);
        }
    };

    float4 O[2][8];
    float  m[2][2], l[2][2];
    #pragma unroll
    for (int a = 0; a < 2; a++) {
        #pragma unroll
        for (int i = 0; i < 8; i++) O[a][i] = make_float4(0.f, 0.f, 0.f, 0.f);
        m[a][0] = m[a][1] = -1e30f;
        l[a][0] = l[a][1] = 0.f;
    }

    const int ktmax = qt * 2 + 1;

    pref(0, 0); CP_COMMIT();
    pref(1, 1); CP_COMMIT();

    for (int kt = 0; kt <= ktmax; kt++) {
        if (kt < ktmax) { CP_WAIT(1); } else { CP_WAIT(0); }
        __syncthreads();
        if (kt + 2 <= ktmax) { pref((kt + 2) % 3, kt + 2); CP_COMMIT(); }

        // a-tile activity: tile fully masked iff smallest key > largest row
        const int base0 = qt * 128 + warp * 32;          // a=0 first row
        const bool act0 = (kt * 64 <= base0 + 15);
        const bool act1 = (kt * 64 <= base0 + 31);       // a=1 rows base0+16..+31
        if (!act1) continue;                             // whole warp-tile masked

        const float* Khi = smp + (kt % 3) * 8704;
        const float* Vt  = Khi + 4352;

        // --- scores: both A-tiles share each B-fragment load ---
        float4 S[2][8];
        #pragma unroll
        for (int a = 0; a < 2; a++)
            #pragma unroll
            for (int i = 0; i < 8; i++) S[a][i] = make_float4(0.f, 0.f, 0.f, 0.f);

        #pragma unroll
        for (int ks = 0; ks < 8; ks++) {
            #pragma unroll
            for (int n8 = 0; n8 < 8; n8++) {
                const int off = (n8 * 8 + g) * 68 + ks * 8 + t;
                uint32_t b0 = __float_as_uint(Khi[off]);
                uint32_t b1 = __float_as_uint(Khi[off + 4]);
                if (act0)
                    mma_tf32(S[0][n8], qa[0][ks][0], qa[0][ks][1], qa[0][ks][2], qa[0][ks][3], b0, b1);
                mma_tf32(S[1][n8], qa[1][ks][0], qa[1][ks][1], qa[1][ks][2], qa[1][ks][3], b0, b1);
            }
        }

        // --- causal mask (mask whenever tile max key exceeds a-tile first row) ---
        #pragma unroll
        for (int a = 0; a < 2; a++) {
            if (a == 0 && !act0) continue;
            const int base = base0 + a * 16;
            if (kt * 64 + 63 > base) {
                const int r0 = base + g;
                #pragma unroll
                for (int n8 = 0; n8 < 8; n8++) {
                    int c0 = kt * 64 + n8 * 8 + 2 * t;
                    if (c0     > r0    ) S[a][n8].x = -1e30f;
                    if (c0 + 1 > r0    ) S[a][n8].y = -1e30f;
                    if (c0     > r0 + 8) S[a][n8].z = -1e30f;
                    if (c0 + 1 > r0 + 8) S[a][n8].w = -1e30f;
                }
            }
        }

        // --- online softmax per a-tile ---
        #pragma unroll
        for (int a = 0; a < 2; a++) {
            if (a == 0 && !act0) continue;
            float mx0 = -1e30f, mx1 = -1e30f;
            #pragma unroll
            for (int n8 = 0; n8 < 8; n8++) {
                mx0 = fmaxf(mx0, fmaxf(S[a][n8].x, S[a][n8].y));
                mx1 = fmaxf(mx1, fmaxf(S[a][n8].z, S[a][n8].w));
            }
            mx0 = fmaxf(mx0, __shfl_xor_sync(0xffffffffu, mx0, 1));
            mx0 = fmaxf(mx0, __shfl_xor_sync(0xffffffffu, mx0, 2));
            mx1 = fmaxf(mx1, __shfl_xor_sync(0xffffffffu, mx1, 1));
            mx1 = fmaxf(mx1, __shfl_xor_sync(0xffffffffu, mx1, 2));

            float nm0 = fmaxf(m[a][0], mx0);
            float nm1 = fmaxf(m[a][1], mx1);
            float c0 = __expf(m[a][0] - nm0);
            float c1 = __expf(m[a][1] - nm1);
            m[a][0] = nm0; m[a][1] = nm1;
            l[a][0] *= c0; l[a][1] *= c1;

            #pragma unroll
            for (int n8 = 0; n8 < 8; n8++) {
                S[a][n8].x = __expf(S[a][n8].x - nm0);
                S[a][n8].y = __expf(S[a][n8].y - nm0);
                S[a][n8].z = __expf(S[a][n8].z - nm1);
                S[a][n8].w = __expf(S[a][n8].w - nm1);
                l[a][0] += S[a][n8].x + S[a][n8].y;
                l[a][1] += S[a][n8].z + S[a][n8].w;
                O[a][n8].x *= c0; O[a][n8].y *= c0;
                O[a][n8].z *= c1; O[a][n8].w *= c1;
            }
        }

        // --- O += P V (B-fragments shared across the two a-tiles) ---
        const int slBase = (lane & ~3) | (t >> 1);
        #pragma unroll
        for (int ks = 0; ks < 8; ks++) {
            uint32_t pa[2][4];
            #pragma unroll
            for (int a = 0; a < 2; a++) {
                if (a == 0 && !act0) continue;
                float x0 = __shfl_sync(0xffffffffu, S[a][ks].x, slBase);
                float y0 = __shfl_sync(0xffffffffu, S[a][ks].y, slBase);
                float z0 = __shfl_sync(0xffffffffu, S[a][ks].z, slBase);
                float w0 = __shfl_sync(0xffffffffu, S[a][ks].w, slBase);
                float x1 = __shfl_sync(0xffffffffu, S[a][ks].x, slBase + 2);
                float y1 = __shfl_sync(0xffffffffu, S[a][ks].y, slBase + 2);
                float z1 = __shfl_sync(0xffffffffu, S[a][ks].z, slBase + 2);
                float w1 = __shfl_sync(0xffffffffu, S[a][ks].w, slBase + 2);
                pa[a][0] = __float_as_uint(f2tf32((t & 1) ? y0 : x0));
                pa[a][1] = __float_as_uint(f2tf32((t & 1) ? w0 : z0));
                pa[a][2] = __float_as_uint(f2tf32((t & 1) ? y1 : x1));
                pa[a][3] = __float_as_uint(f2tf32((t & 1) ? w1 : z1));
            }
            #pragma unroll
            for (int n8 = 0; n8 < 8; n8++) {
                const int off = (n8 * 8 + g) * 68 + ks * 8 + t;
                uint32_t b0 = __float_as_uint(Vt[off]);
                uint32_t b1 = __float_as_uint(Vt[off + 4]);
                if (act0)
                    mma_tf32(O[0][n8], pa[0][0], pa[0][1], pa[0][2], pa[0][3], b0, b1);
                mma_tf32(O[1][n8], pa[1][0], pa[1][1], pa[1][2], pa[1][3], b0, b1);
            }
        }
    }

    // normalize + store (tf32-rounded for the proj GEMM)
    #pragma unroll
    for (int a = 0; a < 2; a++) {
        float l0 = l[a][0], l1 = l[a][1];
        l0 += __shfl_xor_sync(0xffffffffu, l0, 1);
        l0 += __shfl_xor_sync(0xffffffffu, l0, 2);
        l1 += __shfl_xor_sync(0xffffffffu, l1, 1);
        l1 += __shfl_xor_sync(0xffffffffu, l1, 2);
        const float i0 = 1.0f / l0;
        const float i1 = 1.0f / l1;

        float* ob = g_att + ((size_t)bb * T + (size_t)qt * 128 + warp * 32 + a * 16 + g) * C + h * 64;
        #pragma unroll
        for (int n8 = 0; n8 < 8; n8++) {
            *(float2*)&ob[n8 * 8 + 2 * t] =
                make_float2(f2tf32(O[a][n8].x * i0), f2tf32(O[a][n8].y * i0));
            *(float2*)&ob[8 * C + n8 * 8 + 2 * t] =
                make_float2(f2tf32(O[a][n8].z * i1), f2tf32(O[a][n8].w * i1));
        }
    }
}

// ---------------------------------------------------------------------------
extern "C" void kernel_launch(void* const* d_in, const int* in_sizes, int n_in,
                              void* d_out, int out_size)
{
    const float* x  = (const float*)d_in[0];
    const float* Wq = (const float*)d_in[1];
    const float* bq = (const float*)d_in[2];
    const float* Wk = (const float*)d_in[3];
    const float* bk = (const float*)d_in[4];
    const float* Wv = (const float*)d_in[5];
    const float* bv = (const float*)d_in[6];
    const float* Wp = (const float*)d_in[7];
    const float* bp = (const float*)d_in[8];
    float* out = (float*)d_out;

    const int GEMM_SMEM = 3 * STAGE_FLOATS * sizeof(float);   // 107520 B
    const int ATTN_SMEM = 3 * 8704 * sizeof(float);           // 104448 B

    cudaFuncSetAttribute(gemm_tc<1>, cudaFuncAttributeMaxDynamicSharedMemorySize, GEMM_SMEM);
    cudaFuncSetAttribute(gemm_tc<0>, cudaFuncAttributeMaxDynamicSharedMemorySize, GEMM_SMEM);
    cudaFuncSetAttribute(attn_tc,    cudaFuncAttributeMaxDynamicSharedMemorySize, ATTN_SMEM);

    cvt_all<<<12288, 256>>>(x, Wq, Wk, Wv, Wp);

    dim3 gq(24, M / 128);   // fused QKV
    gemm_tc<1><<<gq, 128, GEMM_SMEM>>>(bq, bk, bv, nullptr);

    dim3 ga(T / 128, NH, Bz);   // 16 x 16 x 4
    attn_tc<<<ga, 128, ATTN_SMEM>>>();

    dim3 gp(8, M / 128);
    gemm_tc<0><<<gp, 128, GEMM_SMEM>>>(bp, nullptr, nullptr, out);
}

// round 11
// speedup vs baseline: 1.0807x; 1.0807x over previous
#include <cuda_runtime.h>
#include <math.h>
#include <stdint.h>

#define Bz 4
#define T 2048
#define C 1024
#define NH 16
#define HS 64
#define M (Bz*T)

// ---------------- scratch (__device__ globals: allocation-free rule) --------
// Packed-fragment layouts:
//  A-pack (g_x, g_att): [mtile(M/128)][kchunk(C/32)][m16(8)][k8(4)][lane(32)][comp(4)]
//     comp = hf*2 + rh : (g,t),(g+8,t),(g,t+4),(g+8,t+4)
//  B-pack (g_w*): [ntile(8)][kchunk(32)][n8(16)][k8(4)][lane(32)][comp(2)]
//     comp = hf : (n=g,k=t),(n=g,k=t+4)
__device__ float g_q[Bz*NH*T*HS];    // [B,NH,T,HS] fp32, RoPE'd
__device__ float g_k[Bz*NH*T*HS];    // [B,NH,T,HS] tf32, RoPE'd
__device__ float g_v[Bz*NH*T*HS];    // [B,NH,HS,T] tf32, transposed
__device__ float g_att[M*C];         // A-packed, tf32
__device__ float g_x [M*C];          // A-packed, tf32
__device__ float g_wq[C*C];          // B-packed (W^T), tf32
__device__ float g_wk[C*C];
__device__ float g_wv[C*C];
__device__ float g_wp[C*C];

// ---------------- helpers ----------------------------------------------------
__device__ __forceinline__ float f2tf32(float f) {
    uint32_t u;
    asm("cvt.rna.tf32.f32 %0, %1;" : "=r"(u) : "f"(f));
    return __uint_as_float(u);
}

__device__ __forceinline__ void mma_tf32(float4 &d,
    uint32_t a0, uint32_t a1, uint32_t a2, uint32_t a3,
    uint32_t b0, uint32_t b1)
{
    asm volatile(
        "mma.sync.aligned.m16n8k8.row.col.f32.tf32.tf32.f32 "
        "{%0,%1,%2,%3}, {%4,%5,%6,%7}, {%8,%9}, {%0,%1,%2,%3};\n"
        : "+f"(d.x), "+f"(d.y), "+f"(d.z), "+f"(d.w)
        : "r"(a0), "r"(a1), "r"(a2), "r"(a3), "r"(b0), "r"(b1));
}

__device__ __forceinline__ void cp16(float* smem_dst, const float* gsrc) {
    uint32_t s = (uint32_t)__cvta_generic_to_shared(smem_dst);
    asm volatile("cp.async.cg.shared.global [%0], [%1], 16;" :: "r"(s), "l"(gsrc));
}
#define CP_COMMIT()  asm volatile("cp.async.commit_group;" ::: "memory")
#define CP_WAIT(N)   asm volatile("cp.async.wait_group %0;" :: "n"(N) : "memory")

// ---------------- prep kernels ----------------------------------------------
// X -> A-packed tf32
__global__ void cvt_x(const float* __restrict__ x) {
    int i = blockIdx.x * 256 + threadIdx.x;     // one float4 of input
    int m  = i >> 8;                 // / (C/4)
    int k  = (i & 255) * 4;
    float4 v = *(const float4*)&x[(size_t)m * C + k];

    int mtile = m >> 7, m16l = (m >> 4) & 7, rh = (m >> 3) & 1, gp = m & 7;
    int kch = k >> 5, k8l = (k >> 3) & 3, hf = (k >> 2) & 1;
    size_t base = ((((size_t)mtile * 32 + kch) * 8 + m16l) * 4 + k8l) * 128
                + gp * 16 + hf * 2 + rh;
    g_x[base +  0] = f2tf32(v.x);
    g_x[base +  4] = f2tf32(v.y);
    g_x[base +  8] = f2tf32(v.z);
    g_x[base + 12] = f2tf32(v.w);
}

// W -> B-packed (transposed) tf32; block (32,8), grid (32,32)
__global__ void wtr(const float* __restrict__ src, float* __restrict__ dst) {
    __shared__ float ts[32][33];
    const int bx = blockIdx.x * 32, by = blockIdx.y * 32;
    const int tx = threadIdx.x, ty = threadIdx.y;
    #pragma unroll
    for (int i = 0; i < 4; i++)
        ts[ty + 8 * i][tx] = src[(size_t)(by + ty + 8 * i) * C + bx + tx];
    __syncthreads();
    #pragma unroll
    for (int i = 0; i < 4; i++) {
        int n = bx + ty + 8 * i;     // output row (W^T row) = W col
        int k = by + tx;
        float val = ts[tx][ty + 8 * i];
        int ntile = n >> 7, n8 = (n >> 3) & 15, gp = n & 7;
        int kch = k >> 5, k8l = (k >> 3) & 3, c = k & 7, tp = c & 3, hf = c >> 2;
        size_t off = ((((size_t)ntile * 32 + kch) * 16 + n8) * 4 + k8l) * 64
                   + (gp * 4 + tp) * 2 + hf;
        dst[off] = f2tf32(val);
    }
}

// ---------------- GEMM: packed fragments, 3-stage cp.async ring --------------
// 256 threads, 8 warps, warp tile 64x32, block 128x128, BK=32.
// Stage = A chunk (4096 f) + B chunk (4096 f) = 32 KB. 3 stages.
#define PSTG 8192
#define GEMM_SMEM (3 * PSTG * 4)   // 98304 B

template<int QKV>
__global__ __launch_bounds__(256, 2)
void gemm_tc(const float* __restrict__ b0p,
             const float* __restrict__ b1p,
             const float* __restrict__ b2p,
             float* __restrict__ outp)
{
    extern __shared__ float smp[];

    const float* Apk;
    const float* Bpk;
    const float* bias;
    int sel, ntile;
    if (QKV) {
        Apk = g_x;
        sel = blockIdx.x >> 3;
        ntile = blockIdx.x & 7;
        Bpk  = (sel == 0) ? g_wq : (sel == 1) ? g_wk : g_wv;
        bias = (sel == 0) ? b0p  : (sel == 1) ? b1p  : b2p;
    } else {
        Apk = g_att;
        sel = 3;
        ntile = blockIdx.x;
        Bpk = g_wp; bias = b0p;
    }
    const int mtile = blockIdx.y;
    const int tileM = mtile * 128;
    const int tileN = ntile * 128;

    const int tid   = threadIdx.x;
    const int lane  = tid & 31;
    const int warp  = tid >> 5;
    const int warpM = warp >> 2;     // 0..1
    const int warpN = warp & 3;      // 0..3
    const int g     = lane >> 2;
    const int t     = lane & 3;

    float4 acc[4][4];
    #pragma unroll
    for (int i = 0; i < 4; i++)
        #pragma unroll
        for (int j = 0; j < 4; j++)
            acc[i][j] = make_float4(0.f, 0.f, 0.f, 0.f);

    auto pref = [&](int s, int j) {
        float* As = smp + s * PSTG;
        float* Bs = As + 4096;
        const float* ap = Apk + ((size_t)mtile * 32 + j) * 4096;
        const float* bp = Bpk + ((size_t)ntile * 32 + j) * 4096;
        #pragma unroll
        for (int i = 0; i < 4; i++) {
            int idx = (tid + i * 256) * 4;
            cp16(&As[idx], ap + idx);
            cp16(&Bs[idx], bp + idx);
        }
    };

    pref(0, 0); CP_COMMIT();
    pref(1, 1); CP_COMMIT();

    for (int it = 0; it < 32; it++) {
        if (it < 31) { CP_WAIT(1); } else { CP_WAIT(0); }
        __syncthreads();
        if (it + 2 < 32) { pref((it + 2) % 3, it + 2); CP_COMMIT(); }

        const float4* As = (const float4*)(smp + (it % 3) * PSTG);
        const float2* Bs = (const float2*)(smp + (it % 3) * PSTG + 4096);

        #pragma unroll
        for (int ks = 0; ks < 4; ks++) {
            uint32_t af[4][4];
            uint32_t bfr[4][2];
            #pragma unroll
            for (int mf = 0; mf < 4; mf++) {
                float4 v = As[((warpM * 4 + mf) * 4 + ks) * 32 + lane];
                af[mf][0] = __float_as_uint(v.x);
                af[mf][1] = __float_as_uint(v.y);
                af[mf][2] = __float_as_uint(v.z);
                af[mf][3] = __float_as_uint(v.w);
            }
            #pragma unroll
            for (int nf = 0; nf < 4; nf++) {
                float2 v = Bs[((warpN * 4 + nf) * 4 + ks) * 32 + lane];
                bfr[nf][0] = __float_as_uint(v.x);
                bfr[nf][1] = __float_as_uint(v.y);
            }
            #pragma unroll
            for (int mf = 0; mf < 4; mf++)
                #pragma unroll
                for (int nf = 0; nf < 4; nf++)
                    mma_tf32(acc[mf][nf],
                             af[mf][0], af[mf][1], af[mf][2], af[mf][3],
                             bfr[nf][0], bfr[nf][1]);
        }
    }

    // epilogue (round-8 proven)
    #pragma unroll
    for (int nf = 0; nf < 4; nf++) {
        const int n0 = tileN + warpN * 32 + nf * 8 + t * 2;
        const float bv0 = bias[n0];
        const float bv1 = bias[n0 + 1];
        float inv = 0.f;
        if (QKV) {
            const int ip = (n0 & 63) >> 1;
            inv = powf(10000.0f, -(float)ip / 32.0f);
        }
        #pragma unroll
        for (int mf = 0; mf < 4; mf++) {
            float4 a = acc[mf][nf];
            const int r0 = tileM + warpM * 64 + mf * 16 + g;
            float x0 = a.x + bv0, x1 = a.y + bv1;
            float y0 = a.z + bv0, y1 = a.w + bv1;
            if (!QKV) {
                *(float2*)&outp[(size_t)r0 * C + n0]       = make_float2(x0, x1);
                *(float2*)&outp[(size_t)(r0 + 8) * C + n0] = make_float2(y0, y1);
            } else {
                const int bb = r0 / T;
                const int t0 = r0 % T;
                const int h  = n0 >> 6;
                const int d0 = n0 & 63;
                if (sel < 2) {
                    float sn, cs;
                    sincosf((float)t0 * inv, &sn, &cs);
                    float u0 = x0 * cs - x1 * sn;
                    float u1 = x0 * sn + x1 * cs;
                    x0 = u0; x1 = u1;
                    sincosf((float)(t0 + 8) * inv, &sn, &cs);
                    float w0 = y0 * cs - y1 * sn;
                    float w1 = y0 * sn + y1 * cs;
                    y0 = w0; y1 = w1;
                }
                if (sel == 0) {
                    float* dst = g_q + (((size_t)bb * NH + h) * T + t0) * HS + d0;
                    *(float2*)dst            = make_float2(x0, x1);
                    *(float2*)(dst + 8 * HS) = make_float2(y0, y1);
                } else if (sel == 1) {
                    float* dst = g_k + (((size_t)bb * NH + h) * T + t0) * HS + d0;
                    *(float2*)dst            = make_float2(f2tf32(x0), f2tf32(x1));
                    *(float2*)(dst + 8 * HS) = make_float2(f2tf32(y0), f2tf32(y1));
                } else {
                    float* vd = &g_v[(((size_t)bb * NH + h) * HS + d0) * T + t0];
                    vd[0]     = f2tf32(x0);
                    vd[T]     = f2tf32(x1);
                    vd[8]     = f2tf32(y0);
                    vd[T + 8] = f2tf32(y1);
                }
            }
        }
    }
}

// ---------------- flash attention (round-8 proven; packed g_att store) -------
__global__ __launch_bounds__(128, 2)
void attn_tc()
{
    extern __shared__ float smp[];   // 3 x 8704 floats

    const int qt   = gridDim.x - 1 - blockIdx.x;
    const int h    = blockIdx.y;
    const int bb   = blockIdx.z;
    const int tid  = threadIdx.x;
    const int lane = tid & 31;
    const int warp = tid >> 5;
    const int g    = lane >> 2;
    const int t    = lane & 3;

    const float* kbase = g_k + (size_t)(bb * NH + h) * T * HS;
    const float* vbase = g_v + (size_t)(bb * NH + h) * HS * T;
    const float* qbase = g_q + ((size_t)(bb * NH + h) * T + (size_t)qt * 128) * HS;

    uint32_t qa[2][8][4];
    #pragma unroll
    for (int a = 0; a < 2; a++) {
        const int base = warp * 32 + a * 16;
        #pragma unroll
        for (int ks = 0; ks < 8; ks++) {
            qa[a][ks][0] = __float_as_uint(f2tf32(qbase[(size_t)(base + g)     * HS + ks * 8 + t]     * 0.125f));
            qa[a][ks][1] = __float_as_uint(f2tf32(qbase[(size_t)(base + g + 8) * HS + ks * 8 + t]     * 0.125f));
            qa[a][ks][2] = __float_as_uint(f2tf32(qbase[(size_t)(base + g)     * HS + ks * 8 + t + 4] * 0.125f));
            qa[a][ks][3] = __float_as_uint(f2tf32(qbase[(size_t)(base + g + 8) * HS + ks * 8 + t + 4] * 0.125f));
        }
    }

    auto pref = [&](int s, int kt) {
        float* Kh = smp + s * 8704;
        float* Vv = Kh + 4352;
        #pragma unroll
        for (int i = 0; i < 8; i++) {
            int idx = tid + i * 128;
            int r  = idx >> 4;
            int c4 = (idx & 15) * 4;
            cp16(&Kh[r * 68 + c4], kbase + (size_t)(kt * 64 + r) * HS + c4);
            cp16(&Vv[r * 68 + c4], vbase + (size_t)r * T + kt * 64 + c4);
        }
    };

    float4 O[2][8];
    float  m[2][2], l[2][2];
    #pragma unroll
    for (int a = 0; a < 2; a++) {
        #pragma unroll
        for (int i = 0; i < 8; i++) O[a][i] = make_float4(0.f, 0.f, 0.f, 0.f);
        m[a][0] = m[a][1] = -1e30f;
        l[a][0] = l[a][1] = 0.f;
    }

    const int ktmax = qt * 2 + 1;

    pref(0, 0); CP_COMMIT();
    pref(1, 1); CP_COMMIT();

    for (int kt = 0; kt <= ktmax; kt++) {
        if (kt < ktmax) { CP_WAIT(1); } else { CP_WAIT(0); }
        __syncthreads();
        if (kt + 2 <= ktmax) { pref((kt + 2) % 3, kt + 2); CP_COMMIT(); }

        const int base0 = qt * 128 + warp * 32;
        const bool act0 = (kt * 64 <= base0 + 15);
        const bool act1 = (kt * 64 <= base0 + 31);
        if (!act1) continue;

        const float* Khi = smp + (kt % 3) * 8704;
        const float* Vt  = Khi + 4352;

        float4 S[2][8];
        #pragma unroll
        for (int a = 0; a < 2; a++)
            #pragma unroll
            for (int i = 0; i < 8; i++) S[a][i] = make_float4(0.f, 0.f, 0.f, 0.f);

        #pragma unroll
        for (int ks = 0; ks < 8; ks++) {
            #pragma unroll
            for (int n8 = 0; n8 < 8; n8++) {
                const int off = (n8 * 8 + g) * 68 + ks * 8 + t;
                uint32_t b0 = __float_as_uint(Khi[off]);
                uint32_t b1 = __float_as_uint(Khi[off + 4]);
                if (act0)
                    mma_tf32(S[0][n8], qa[0][ks][0], qa[0][ks][1], qa[0][ks][2], qa[0][ks][3], b0, b1);
                mma_tf32(S[1][n8], qa[1][ks][0], qa[1][ks][1], qa[1][ks][2], qa[1][ks][3], b0, b1);
            }
        }

        #pragma unroll
        for (int a = 0; a < 2; a++) {
            if (a == 0 && !act0) continue;
            const int base = base0 + a * 16;
            if (kt * 64 + 63 > base) {
                const int r0 = base + g;
                #pragma unroll
                for (int n8 = 0; n8 < 8; n8++) {
                    int c0 = kt * 64 + n8 * 8 + 2 * t;
                    if (c0     > r0    ) S[a][n8].x = -1e30f;
                    if (c0 + 1 > r0    ) S[a][n8].y = -1e30f;
                    if (c0     > r0 + 8) S[a][n8].z = -1e30f;
                    if (c0 + 1 > r0 + 8) S[a][n8].w = -1e30f;
                }
            }
        }

        #pragma unroll
        for (int a = 0; a < 2; a++) {
            if (a == 0 && !act0) continue;
            float mx0 = -1e30f, mx1 = -1e30f;
            #pragma unroll
            for (int n8 = 0; n8 < 8; n8++) {
                mx0 = fmaxf(mx0, fmaxf(S[a][n8].x, S[a][n8].y));
                mx1 = fmaxf(mx1, fmaxf(S[a][n8].z, S[a][n8].w));
            }
            mx0 = fmaxf(mx0, __shfl_xor_sync(0xffffffffu, mx0, 1));
            mx0 = fmaxf(mx0, __shfl_xor_sync(0xffffffffu, mx0, 2));
            mx1 = fmaxf(mx1, __shfl_xor_sync(0xffffffffu, mx1, 1));
            mx1 = fmaxf(mx1, __shfl_xor_sync(0xffffffffu, mx1, 2));

            float nm0 = fmaxf(m[a][0], mx0);
            float nm1 = fmaxf(m[a][1], mx1);
            float c0 = __expf(m[a][0] - nm0);
            float c1 = __expf(m[a][1] - nm1);
            m[a][0] = nm0; m[a][1] = nm1;
            l[a][0] *= c0; l[a][1] *= c1;

            #pragma unroll
            for (int n8 = 0; n8 < 8; n8++) {
                S[a][n8].x = __expf(S[a][n8].x - nm0);
                S[a][n8].y = __expf(S[a][n8].y - nm0);
                S[a][n8].z = __expf(S[a][n8].z - nm1);
                S[a][n8].w = __expf(S[a][n8].w - nm1);
                l[a][0] += S[a][n8].x + S[a][n8].y;
                l[a][1] += S[a][n8].z + S[a][n8].w;
                O[a][n8].x *= c0; O[a][n8].y *= c0;
                O[a][n8].z *= c1; O[a][n8].w *= c1;
            }
        }

        const int slBase = (lane & ~3) | (t >> 1);
        #pragma unroll
        for (int ks = 0; ks < 8; ks++) {
            uint32_t pa[2][4];
            #pragma unroll
            for (int a = 0; a < 2; a++) {
                if (a == 0 && !act0) continue;
                float x0 = __shfl_sync(0xffffffffu, S[a][ks].x, slBase);
                float y0 = __shfl_sync(0xffffffffu, S[a][ks].y, slBase);
                float z0 = __shfl_sync(0xffffffffu, S[a][ks].z, slBase);
                float w0 = __shfl_sync(0xffffffffu, S[a][ks].w, slBase);
                float x1 = __shfl_sync(0xffffffffu, S[a][ks].x, slBase + 2);
                float y1 = __shfl_sync(0xffffffffu, S[a][ks].y, slBase + 2);
                float z1 = __shfl_sync(0xffffffffu, S[a][ks].z, slBase + 2);
                float w1 = __shfl_sync(0xffffffffu, S[a][ks].w, slBase + 2);
                pa[a][0] = __float_as_uint(f2tf32((t & 1) ? y0 : x0));
                pa[a][1] = __float_as_uint(f2tf32((t & 1) ? w0 : z0));
                pa[a][2] = __float_as_uint(f2tf32((t & 1) ? y1 : x1));
                pa[a][3] = __float_as_uint(f2tf32((t & 1) ? w1 : z1));
            }
            #pragma unroll
            for (int n8 = 0; n8 < 8; n8++) {
                const int off = (n8 * 8 + g) * 68 + ks * 8 + t;
                uint32_t b0 = __float_as_uint(Vt[off]);
                uint32_t b1 = __float_as_uint(Vt[off + 4]);
                if (act0)
                    mma_tf32(O[0][n8], pa[0][0], pa[0][1], pa[0][2], pa[0][3], b0, b1);
                mma_tf32(O[1][n8], pa[1][0], pa[1][1], pa[1][2], pa[1][3], b0, b1);
            }
        }
    }

    // normalize + store into A-packed g_att (tf32) for the proj GEMM
    #pragma unroll
    for (int a = 0; a < 2; a++) {
        float l0 = l[a][0], l1 = l[a][1];
        l0 += __shfl_xor_sync(0xffffffffu, l0, 1);
        l0 += __shfl_xor_sync(0xffffffffu, l0, 2);
        l1 += __shfl_xor_sync(0xffffffffu, l1, 1);
        l1 += __shfl_xor_sync(0xffffffffu, l1, 2);
        const float i0 = 1.0f / l0;
        const float i1 = 1.0f / l1;

        const int mtile = bb * 16 + qt;            // global row / 128
        const int m16l  = warp * 2 + a;
        const int c0 = 2 * t, c1 = 2 * t + 1;
        const int i0x = (g * 4 + (c0 & 3)) * 4 + (c0 >> 2) * 2;
        const int i1x = (g * 4 + (c1 & 3)) * 4 + (c1 >> 2) * 2;

        #pragma unroll
        for (int n8 = 0; n8 < 8; n8++) {
            const int kch = h * 2 + (n8 >> 2);
            const int k8l = n8 & 3;
            float* fb = g_att +
                ((((size_t)mtile * 32 + kch) * 8 + m16l) * 4 + k8l) * 128;
            fb[i0x]     = f2tf32(O[a][n8].x * i0);   // (row g,   col 2t)
            fb[i0x + 1] = f2tf32(O[a][n8].z * i1);   // (row g+8, col 2t)
            fb[i1x]     = f2tf32(O[a][n8].y * i0);   // (row g,   col 2t+1)
            fb[i1x + 1] = f2tf32(O[a][n8].w * i1);   // (row g+8, col 2t+1)
        }
    }
}

// ---------------------------------------------------------------------------
extern "C" void kernel_launch(void* const* d_in, const int* in_sizes, int n_in,
                              void* d_out, int out_size)
{
    const float* x  = (const float*)d_in[0];
    const float* Wq = (const float*)d_in[1];
    const float* bq = (const float*)d_in[2];
    const float* Wk = (const float*)d_in[3];
    const float* bk = (const float*)d_in[4];
    const float* Wv = (const float*)d_in[5];
    const float* bv = (const float*)d_in[6];
    const float* Wp = (const float*)d_in[7];
    const float* bp = (const float*)d_in[8];
    float* out = (float*)d_out;

    float* d_gwq; cudaGetSymbolAddress((void**)&d_gwq, g_wq);
    float* d_gwk; cudaGetSymbolAddress((void**)&d_gwk, g_wk);
    float* d_gwv; cudaGetSymbolAddress((void**)&d_gwv, g_wv);
    float* d_gwp; cudaGetSymbolAddress((void**)&d_gwp, g_wp);

    const int ATTN_SMEM = 3 * 8704 * sizeof(float);   // 104448 B

    cudaFuncSetAttribute(gemm_tc<1>, cudaFuncAttributeMaxDynamicSharedMemorySize, GEMM_SMEM);
    cudaFuncSetAttribute(gemm_tc<0>, cudaFuncAttributeMaxDynamicSharedMemorySize, GEMM_SMEM);
    cudaFuncSetAttribute(attn_tc,    cudaFuncAttributeMaxDynamicSharedMemorySize, ATTN_SMEM);

    // prep: pack X (A-layout) and W^T's (B-layout), tf32-rounded
    cvt_x<<<M * C / 1024, 256>>>(x);
    dim3 tb(32, 8), tg(32, 32);
    wtr<<<tg, tb>>>(Wq, d_gwq);
    wtr<<<tg, tb>>>(Wk, d_gwk);
    wtr<<<tg, tb>>>(Wv, d_gwv);
    wtr<<<tg, tb>>>(Wp, d_gwp);

    dim3 gq(24, M / 128);   // fused QKV: 3 mats x 8 n-tiles, 64 m-tiles
    gemm_tc<1><<<gq, 256, GEMM_SMEM>>>(bq, bk, bv, nullptr);

    dim3 ga(T / 128, NH, Bz);   // 16 x 16 x 4
    attn_tc<<<ga, 128, ATTN_SMEM>>>();

    dim3 gp(8, M / 128);
    gemm_tc<0><<<gp, 256, GEMM_SMEM>>>(bp, nullptr, nullptr, out);
}

// round 12
// speedup vs baseline: 1.9825x; 1.8345x over previous
#include <cuda_runtime.h>
#include <cuda_fp16.h>
#include <math.h>
#include <stdint.h>

#define Bz 4
#define T 2048
#define C 1024
#define NH 16
#define HS 64
#define M (Bz*T)

// ---------------- scratch (__device__ globals) -------------------------------
// A-pack (fp16, m16n8k16 A-frags): uint4[((mtile*64 + kk)*8 + m16)*32 + lane]
//   uint4 = {a0,a1,a2,a3}: a0={A[g][2t],A[g][2t+1]}, a1=rows+8, a2=cols+8, a3=both
// B-pack (fp16, B-frags): uint2[((ntile*64 + kk)*16 + n8)*32 + lane]
//   b0={W[k0+2t][n], W[k0+2t+1][n]}, b1=k+8 ; n = n8*8+g, k0 = kk*16
__device__ uint4 g_x  [64*64*8*32];    // X packed (16 MB)
__device__ uint4 g_att[64*64*8*32];    // attention out packed (16 MB)
__device__ uint2 g_wq [8*64*16*32];    // 2 MB each
__device__ uint2 g_wk [8*64*16*32];
__device__ uint2 g_wv [8*64*16*32];
__device__ uint2 g_wp [8*64*16*32];
__device__ float  g_q[Bz*NH*T*HS];     // [B,NH,T,HS] fp32, RoPE'd
__device__ __half g_k[Bz*NH*T*HS];     // [B,NH,T,HS] fp16, RoPE'd
__device__ __half g_v[Bz*NH*T*HS];     // [B,NH,HS,T] fp16, transposed

// ---------------- helpers ----------------------------------------------------
__device__ __forceinline__ uint32_t h2(float a, float b) {
    __half2 h = __floats2half2_rn(a, b);
    return *(uint32_t*)&h;
}

__device__ __forceinline__ void mma_f16(float4 &d,
    uint32_t a0, uint32_t a1, uint32_t a2, uint32_t a3,
    uint32_t b0, uint32_t b1)
{
    asm volatile(
        "mma.sync.aligned.m16n8k16.row.col.f32.f16.f16.f32 "
        "{%0,%1,%2,%3}, {%4,%5,%6,%7}, {%8,%9}, {%0,%1,%2,%3};\n"
        : "+f"(d.x), "+f"(d.y), "+f"(d.z), "+f"(d.w)
        : "r"(a0), "r"(a1), "r"(a2), "r"(a3), "r"(b0), "r"(b1));
}

__device__ __forceinline__ void cp16b(void* sdst, const void* gsrc) {
    uint32_t s = (uint32_t)__cvta_generic_to_shared(sdst);
    asm volatile("cp.async.cg.shared.global [%0], [%1], 16;" :: "r"(s), "l"(gsrc));
}
#define CP_COMMIT()  asm volatile("cp.async.commit_group;" ::: "memory")
#define CP_WAIT(N)   asm volatile("cp.async.wait_group %0;" :: "n"(N) : "memory")

// ---------------- prep: pack X into A-frag fp16 ------------------------------
__global__ void cvt_x(const float* __restrict__ x) {
    int idx = blockIdx.x * 256 + threadIdx.x;   // 1,048,576 total
    int lane = idx & 31, m16 = (idx >> 5) & 7, kk = (idx >> 8) & 63, mtile = idx >> 14;
    int g = lane >> 2, t = lane & 3;
    const float* p0 = x + (size_t)(mtile * 128 + m16 * 16 + g) * C + kk * 16 + 2 * t;
    const float* p1 = p0 + 8 * C;
    float2 v00 = *(const float2*)p0;
    float2 v10 = *(const float2*)p1;
    float2 v01 = *(const float2*)(p0 + 8);
    float2 v11 = *(const float2*)(p1 + 8);
    g_x[idx] = make_uint4(h2(v00.x, v00.y), h2(v10.x, v10.y),
                          h2(v01.x, v01.y), h2(v11.x, v11.y));
}

// ---------------- prep: pack W into B-frag fp16 ------------------------------
__global__ void wtr(const float* __restrict__ w, uint2* __restrict__ dst) {
    int idx = blockIdx.x * 256 + threadIdx.x;   // 262,144 total
    int lane = idx & 31, n8 = (idx >> 5) & 15, kk = (idx >> 9) & 63, ntile = idx >> 15;
    int g = lane >> 2, t = lane & 3;
    int n = ntile * 128 + n8 * 8 + g;
    const float* p = w + (size_t)(kk * 16 + 2 * t) * C + n;
    dst[idx] = make_uint2(h2(p[0], p[C]), h2(p[8 * C], p[9 * C]));
}

// ---------------- GEMM: fp16 k16, packed frags, 3-stage cp.async ring --------
// 256 thr, 8 warps, warp tile 64x32, block 128x128, BK=32 (2 k16 chunks).
#define GSTG 16384
#define GEMM_SMEM (3 * GSTG)   // 49152 B

template<int QKV>
__global__ __launch_bounds__(256, 2)
void gemm_tc(const float* __restrict__ b0p,
             const float* __restrict__ b1p,
             const float* __restrict__ b2p,
             float* __restrict__ outp)
{
    extern __shared__ char smb[];

    const uint4* Apk;
    const uint2* Bpk;
    const float* bias;
    int sel, ntile;
    if (QKV) {
        Apk = g_x;
        sel = blockIdx.x >> 3;
        ntile = blockIdx.x & 7;
        Bpk  = (sel == 0) ? g_wq : (sel == 1) ? g_wk : g_wv;
        bias = (sel == 0) ? b0p  : (sel == 1) ? b1p  : b2p;
    } else {
        Apk = g_att;
        sel = 3;
        ntile = blockIdx.x;
        Bpk = g_wp; bias = b0p;
    }
    const int mtile = blockIdx.y;
    const int tileM = mtile * 128;
    const int tileN = ntile * 128;

    const int tid   = threadIdx.x;
    const int lane  = tid & 31;
    const int warp  = tid >> 5;
    const int warpM = warp >> 2;     // 0..1
    const int warpN = warp & 3;      // 0..3
    const int g     = lane >> 2;
    const int t     = lane & 3;

    float4 acc[4][4];
    #pragma unroll
    for (int i = 0; i < 4; i++)
        #pragma unroll
        for (int j = 0; j < 4; j++)
            acc[i][j] = make_float4(0.f, 0.f, 0.f, 0.f);

    auto pref = [&](int s, int j) {
        char* As = smb + s * GSTG;            // 8192 B (512 uint4)
        char* Bs = As + 8192;                 // 8192 B (1024 uint2)
        const char* ap = (const char*)(Apk + ((size_t)mtile * 64 + 2 * j) * 256);
        const char* bp = (const char*)(Bpk + ((size_t)ntile * 64 + 2 * j) * 512);
        #pragma unroll
        for (int i = 0; i < 2; i++) {
            int o = (tid + i * 256) * 16;
            cp16b(As + o, ap + o);
            cp16b(Bs + o, bp + o);
        }
    };

    pref(0, 0); CP_COMMIT();
    pref(1, 1); CP_COMMIT();

    for (int j = 0; j < 32; j++) {
        if (j < 31) { CP_WAIT(1); } else { CP_WAIT(0); }
        __syncthreads();
        if (j + 2 < 32) { pref((j + 2) % 3, j + 2); CP_COMMIT(); }

        const uint4* As4 = (const uint4*)(smb + (j % 3) * GSTG);
        const uint2* Bs2 = (const uint2*)(smb + (j % 3) * GSTG + 8192);

        #pragma unroll
        for (int kk2 = 0; kk2 < 2; kk2++) {
            uint4 af[4];
            uint2 bf[4];
            #pragma unroll
            for (int mf = 0; mf < 4; mf++)
                af[mf] = As4[(kk2 * 8 + warpM * 4 + mf) * 32 + lane];
            #pragma unroll
            for (int nf = 0; nf < 4; nf++)
                bf[nf] = Bs2[(kk2 * 16 + warpN * 4 + nf) * 32 + lane];
            #pragma unroll
            for (int mf = 0; mf < 4; mf++)
                #pragma unroll
                for (int nf = 0; nf < 4; nf++)
                    mma_f16(acc[mf][nf], af[mf].x, af[mf].y, af[mf].z, af[mf].w,
                            bf[nf].x, bf[nf].y);
        }
    }

    // epilogue
    #pragma unroll
    for (int nf = 0; nf < 4; nf++) {
        const int n0 = tileN + warpN * 32 + nf * 8 + t * 2;
        const float bv0 = bias[n0];
        const float bv1 = bias[n0 + 1];
        float inv = 0.f;
        if (QKV) {
            const int ip = (n0 & 63) >> 1;
            inv = powf(10000.0f, -(float)ip / 32.0f);
        }
        #pragma unroll
        for (int mf = 0; mf < 4; mf++) {
            float4 a = acc[mf][nf];
            const int r0 = tileM + warpM * 64 + mf * 16 + g;
            float x0 = a.x + bv0, x1 = a.y + bv1;
            float y0 = a.z + bv0, y1 = a.w + bv1;
            if (!QKV) {
                *(float2*)&outp[(size_t)r0 * C + n0]       = make_float2(x0, x1);
                *(float2*)&outp[(size_t)(r0 + 8) * C + n0] = make_float2(y0, y1);
            } else {
                const int bb = r0 / T;
                const int t0 = r0 % T;
                const int h  = n0 >> 6;
                const int d0 = n0 & 63;
                if (sel < 2) {
                    float sn, cs;
                    sincosf((float)t0 * inv, &sn, &cs);
                    float u0 = x0 * cs - x1 * sn;
                    float u1 = x0 * sn + x1 * cs;
                    x0 = u0; x1 = u1;
                    sincosf((float)(t0 + 8) * inv, &sn, &cs);
                    float w0 = y0 * cs - y1 * sn;
                    float w1 = y0 * sn + y1 * cs;
                    y0 = w0; y1 = w1;
                }
                if (sel == 0) {
                    float* dst = g_q + (((size_t)bb * NH + h) * T + t0) * HS + d0;
                    *(float2*)dst            = make_float2(x0, x1);
                    *(float2*)(dst + 8 * HS) = make_float2(y0, y1);
                } else if (sel == 1) {
                    __half* dst = g_k + (((size_t)bb * NH + h) * T + t0) * HS + d0;
                    *(__half2*)dst            = __floats2half2_rn(x0, x1);
                    *(__half2*)(dst + 8 * HS) = __floats2half2_rn(y0, y1);
                } else {
                    __half* vd = g_v + (((size_t)bb * NH + h) * HS + d0) * T + t0;
                    vd[0]     = __float2half_rn(x0);
                    vd[T]     = __float2half_rn(x1);
                    vd[8]     = __float2half_rn(y0);
                    vd[T + 8] = __float2half_rn(y1);
                }
            }
        }
    }
}

// ---------------- flash attention: fp16 k16, zero-shuffle PV ----------------
// 128 q rows/block, 4 warps, 32 rows/warp (2 m16 a-tiles). K/V tiles 64 keys.
// smem per stage: K [64 keys][72 h] + V [64 d][72 h] = 18432 B, 3 stages.
#define ASTG 18432
#define ATTN_SMEM (3 * ASTG)   // 55296 B

__global__ __launch_bounds__(128, 2)
void attn_tc()
{
    extern __shared__ char smb[];

    const int qt   = gridDim.x - 1 - blockIdx.x;   // big tiles first
    const int h    = blockIdx.y;
    const int bb   = blockIdx.z;
    const int tid  = threadIdx.x;
    const int lane = tid & 31;
    const int warp = tid >> 5;
    const int g    = lane >> 2;
    const int t    = lane & 3;

    const __half* kbase = g_k + (size_t)(bb * NH + h) * T * HS;   // [key][dim]
    const __half* vbase = g_v + (size_t)(bb * NH + h) * HS * T;   // [dim][key]
    const float*  qbase = g_q + ((size_t)(bb * NH + h) * T + (size_t)qt * 128) * HS;

    // Q fragments: 2 a-tiles x 4 k16-chunks x 4 regs (fp16x2), pre-scaled
    uint32_t qa[2][4][4];
    #pragma unroll
    for (int a = 0; a < 2; a++) {
        const int base = warp * 32 + a * 16;
        const float* q0 = qbase + (size_t)(base + g) * HS;
        const float* q1 = q0 + 8 * HS;
        #pragma unroll
        for (int kk = 0; kk < 4; kk++) {
            float2 v00 = *(const float2*)&q0[kk * 16 + 2 * t];
            float2 v10 = *(const float2*)&q1[kk * 16 + 2 * t];
            float2 v01 = *(const float2*)&q0[kk * 16 + 8 + 2 * t];
            float2 v11 = *(const float2*)&q1[kk * 16 + 8 + 2 * t];
            qa[a][kk][0] = h2(v00.x * 0.125f, v00.y * 0.125f);
            qa[a][kk][1] = h2(v10.x * 0.125f, v10.y * 0.125f);
            qa[a][kk][2] = h2(v01.x * 0.125f, v01.y * 0.125f);
            qa[a][kk][3] = h2(v11.x * 0.125f, v11.y * 0.125f);
        }
    }

    auto pref = [&](int s, int kt) {
        char* Kh = smb + s * ASTG;
        char* Vv = Kh + 9216;
        #pragma unroll
        for (int i = 0; i < 4; i++) {
            int idx = tid + i * 128;       // 0..511
            int r = idx >> 3, c = idx & 7;
            cp16b(Kh + r * 144 + c * 16,
                  (const char*)(kbase + (size_t)(kt * 64 + r) * HS) + c * 16);
            cp16b(Vv + r * 144 + c * 16,
                  (const char*)(vbase + (size_t)r * T + kt * 64) + c * 16);
        }
    };

    float4 O[2][8];
    float  m[2][2], l[2][2];
    #pragma unroll
    for (int a = 0; a < 2; a++) {
        #pragma unroll
        for (int i = 0; i < 8; i++) O[a][i] = make_float4(0.f, 0.f, 0.f, 0.f);
        m[a][0] = m[a][1] = -1e30f;
        l[a][0] = l[a][1] = 0.f;
    }

    const int ktmax = qt * 2 + 1;

    pref(0, 0); CP_COMMIT();
    pref(1, 1); CP_COMMIT();

    for (int kt = 0; kt <= ktmax; kt++) {
        if (kt < ktmax) { CP_WAIT(1); } else { CP_WAIT(0); }
        __syncthreads();
        if (kt + 2 <= ktmax) { pref((kt + 2) % 3, kt + 2); CP_COMMIT(); }

        const int base0 = qt * 128 + warp * 32;
        const bool act0 = (kt * 64 <= base0 + 15);
        const bool act1 = (kt * 64 <= base0 + 31);
        if (!act1) continue;

        const __half* Khh = (const __half*)(smb + (kt % 3) * ASTG);
        const __half* Vhh = (const __half*)(smb + (kt % 3) * ASTG + 9216);

        // --- scores: S[a][n8] over 4 k16 chunks ---
        float4 S[2][8];
        #pragma unroll
        for (int a = 0; a < 2; a++)
            #pragma unroll
            for (int i = 0; i < 8; i++) S[a][i] = make_float4(0.f, 0.f, 0.f, 0.f);

        #pragma unroll
        for (int kk = 0; kk < 4; kk++) {
            #pragma unroll
            for (int n8 = 0; n8 < 8; n8++) {
                const int off = (n8 * 8 + g) * 72 + kk * 16 + 2 * t;
                uint32_t b0 = *(const uint32_t*)&Khh[off];
                uint32_t b1 = *(const uint32_t*)&Khh[off + 8];
                if (act0)
                    mma_f16(S[0][n8], qa[0][kk][0], qa[0][kk][1], qa[0][kk][2], qa[0][kk][3], b0, b1);
                mma_f16(S[1][n8], qa[1][kk][0], qa[1][kk][1], qa[1][kk][2], qa[1][kk][3], b0, b1);
            }
        }

        // --- causal mask ---
        #pragma unroll
        for (int a = 0; a < 2; a++) {
            if (a == 0 && !act0) continue;
            const int base = base0 + a * 16;
            if (kt * 64 + 63 > base) {
                const int r0 = base + g;
                #pragma unroll
                for (int n8 = 0; n8 < 8; n8++) {
                    int c0 = kt * 64 + n8 * 8 + 2 * t;
                    if (c0     > r0    ) S[a][n8].x = -1e30f;
                    if (c0 + 1 > r0    ) S[a][n8].y = -1e30f;
                    if (c0     > r0 + 8) S[a][n8].z = -1e30f;
                    if (c0 + 1 > r0 + 8) S[a][n8].w = -1e30f;
                }
            }
        }

        // --- online softmax ---
        #pragma unroll
        for (int a = 0; a < 2; a++) {
            if (a == 0 && !act0) continue;
            float mx0 = -1e30f, mx1 = -1e30f;
            #pragma unroll
            for (int n8 = 0; n8 < 8; n8++) {
                mx0 = fmaxf(mx0, fmaxf(S[a][n8].x, S[a][n8].y));
                mx1 = fmaxf(mx1, fmaxf(S[a][n8].z, S[a][n8].w));
            }
            mx0 = fmaxf(mx0, __shfl_xor_sync(0xffffffffu, mx0, 1));
            mx0 = fmaxf(mx0, __shfl_xor_sync(0xffffffffu, mx0, 2));
            mx1 = fmaxf(mx1, __shfl_xor_sync(0xffffffffu, mx1, 1));
            mx1 = fmaxf(mx1, __shfl_xor_sync(0xffffffffu, mx1, 2));

            float nm0 = fmaxf(m[a][0], mx0);
            float nm1 = fmaxf(m[a][1], mx1);
            float c0 = __expf(m[a][0] - nm0);
            float c1 = __expf(m[a][1] - nm1);
            m[a][0] = nm0; m[a][1] = nm1;
            l[a][0] *= c0; l[a][1] *= c1;

            #pragma unroll
            for (int n8 = 0; n8 < 8; n8++) {
                S[a][n8].x = __expf(S[a][n8].x - nm0);
                S[a][n8].y = __expf(S[a][n8].y - nm0);
                S[a][n8].z = __expf(S[a][n8].z - nm1);
                S[a][n8].w = __expf(S[a][n8].w - nm1);
                l[a][0] += S[a][n8].x + S[a][n8].y;
                l[a][1] += S[a][n8].z + S[a][n8].w;
                O[a][n8].x *= c0; O[a][n8].y *= c0;
                O[a][n8].z *= c1; O[a][n8].w *= c1;
            }
        }

        // --- O += P V : C-frag -> A-frag identity (zero shuffles) ---
        #pragma unroll
        for (int kk = 0; kk < 4; kk++) {
            uint32_t pa[2][4];
            #pragma unroll
            for (int a = 0; a < 2; a++) {
                if (a == 0 && !act0) continue;
                pa[a][0] = h2(S[a][2 * kk].x,     S[a][2 * kk].y);
                pa[a][1] = h2(S[a][2 * kk].z,     S[a][2 * kk].w);
                pa[a][2] = h2(S[a][2 * kk + 1].x, S[a][2 * kk + 1].y);
                pa[a][3] = h2(S[a][2 * kk + 1].z, S[a][2 * kk + 1].w);
            }
            #pragma unroll
            for (int n8 = 0; n8 < 8; n8++) {
                const int off = (n8 * 8 + g) * 72 + kk * 16 + 2 * t;
                uint32_t b0 = *(const uint32_t*)&Vhh[off];
                uint32_t b1 = *(const uint32_t*)&Vhh[off + 8];
                if (act0)
                    mma_f16(O[0][n8], pa[0][0], pa[0][1], pa[0][2], pa[0][3], b0, b1);
                mma_f16(O[1][n8], pa[1][0], pa[1][1], pa[1][2], pa[1][3], b0, b1);
            }
        }
    }

    // normalize + store into A-packed fp16 g_att for the proj GEMM
    #pragma unroll
    for (int a = 0; a < 2; a++) {
        float l0 = l[a][0], l1 = l[a][1];
        l0 += __shfl_xor_sync(0xffffffffu, l0, 1);
        l0 += __shfl_xor_sync(0xffffffffu, l0, 2);
        l1 += __shfl_xor_sync(0xffffffffu, l1, 1);
        l1 += __shfl_xor_sync(0xffffffffu, l1, 2);
        const float i0 = 1.0f / l0;
        const float i1 = 1.0f / l1;

        const int mtile = bb * 16 + qt;
        const int m16   = warp * 2 + a;
        #pragma unroll
        for (int kk = 0; kk < 4; kk++) {
            uint4 u;
            u.x = h2(O[a][2 * kk].x * i0,     O[a][2 * kk].y * i0);
            u.y = h2(O[a][2 * kk].z * i1,     O[a][2 * kk].w * i1);
            u.z = h2(O[a][2 * kk + 1].x * i0, O[a][2 * kk + 1].y * i0);
            u.w = h2(O[a][2 * kk + 1].z * i1, O[a][2 * kk + 1].w * i1);
            g_att[(((size_t)mtile * 64 + h * 4 + kk) * 8 + m16) * 32 + lane] = u;
        }
    }
}

// ---------------------------------------------------------------------------
extern "C" void kernel_launch(void* const* d_in, const int* in_sizes, int n_in,
                              void* d_out, int out_size)
{
    const float* x  = (const float*)d_in[0];
    const float* Wq = (const float*)d_in[1];
    const float* bq = (const float*)d_in[2];
    const float* Wk = (const float*)d_in[3];
    const float* bk = (const float*)d_in[4];
    const float* Wv = (const float*)d_in[5];
    const float* bv = (const float*)d_in[6];
    const float* Wp = (const float*)d_in[7];
    const float* bp = (const float*)d_in[8];
    float* out = (float*)d_out;

    uint2* d_gwq; cudaGetSymbolAddress((void**)&d_gwq, g_wq);
    uint2* d_gwk; cudaGetSymbolAddress((void**)&d_gwk, g_wk);
    uint2* d_gwv; cudaGetSymbolAddress((void**)&d_gwv, g_wv);
    uint2* d_gwp; cudaGetSymbolAddress((void**)&d_gwp, g_wp);

    cudaFuncSetAttribute(gemm_tc<1>, cudaFuncAttributeMaxDynamicSharedMemorySize, GEMM_SMEM);
    cudaFuncSetAttribute(gemm_tc<0>, cudaFuncAttributeMaxDynamicSharedMemorySize, GEMM_SMEM);
    cudaFuncSetAttribute(attn_tc,    cudaFuncAttributeMaxDynamicSharedMemorySize, ATTN_SMEM);

    // prep: pack X (A-frag) and W's (B-frag) in fp16
    cvt_x<<<4096, 256>>>(x);
    wtr<<<1024, 256>>>(Wq, d_gwq);
    wtr<<<1024, 256>>>(Wk, d_gwk);
    wtr<<<1024, 256>>>(Wv, d_gwv);
    wtr<<<1024, 256>>>(Wp, d_gwp);

    dim3 gq(24, M / 128);   // fused QKV
    gemm_tc<1><<<gq, 256, GEMM_SMEM>>>(bq, bk, bv, nullptr);

    dim3 ga(T / 128, NH, Bz);
    attn_tc<<<ga, 128, ATTN_SMEM>>>();

    dim3 gp(8, M / 128);
    gemm_tc<0><<<gp, 256, GEMM_SMEM>>>(bp, nullptr, nullptr, out);
}

// round 13
// speedup vs baseline: 2.2020x; 1.1107x over previous
#include <cuda_runtime.h>
#include <cuda_fp16.h>
#include <math.h>
#include <stdint.h>

#define Bz 4
#define T 2048
#define C 1024
#define NH 16
#define HS 64
#define M (Bz*T)

// ---------------- scratch (__device__ globals) -------------------------------
// A-pack (fp16 m16n8k16 A-frags): uint4[((mtile*64 + kk)*8 + m16)*32 + lane]
// B-pack (fp16 B-frags):          uint2[((ntile*64 + kk)*16 + n8)*32 + lane]
// K/V-pack (attention B-frags, per b*h and 64-key tile):
//   uint2[(((bh*32 + tile)*4 + kk)*256) + n8*32 + lane]
//   K: n=key (n8,g), k=dim (kk chunk, {2t,2t+1 | +8})
//   V: n=dim,        k=key
__device__ uint4 g_x  [64*64*8*32];
__device__ uint4 g_att[64*64*8*32];
__device__ uint2 g_wq [8*64*16*32];
__device__ uint2 g_wk [8*64*16*32];
__device__ uint2 g_wv [8*64*16*32];
__device__ uint2 g_wp [8*64*16*32];
__device__ float  g_q[Bz*NH*T*HS];      // [B,NH,T,HS] fp32, RoPE'd
__device__ uint2  g_kp[64*32*1024];     // K packed (16 MB)
__device__ uint2  g_vp[64*32*1024];     // V packed (16 MB)

// ---------------- helpers ----------------------------------------------------
__device__ __forceinline__ uint32_t h2(float a, float b) {
    __half2 h = __floats2half2_rn(a, b);
    return *(uint32_t*)&h;
}

__device__ __forceinline__ void mma_f16(float4 &d,
    uint32_t a0, uint32_t a1, uint32_t a2, uint32_t a3,
    uint32_t b0, uint32_t b1)
{
    asm volatile(
        "mma.sync.aligned.m16n8k16.row.col.f32.f16.f16.f32 "
        "{%0,%1,%2,%3}, {%4,%5,%6,%7}, {%8,%9}, {%0,%1,%2,%3};\n"
        : "+f"(d.x), "+f"(d.y), "+f"(d.z), "+f"(d.w)
        : "r"(a0), "r"(a1), "r"(a2), "r"(a3), "r"(b0), "r"(b1));
}

__device__ __forceinline__ void cp16b(void* sdst, const void* gsrc) {
    uint32_t s = (uint32_t)__cvta_generic_to_shared(sdst);
    asm volatile("cp.async.cg.shared.global [%0], [%1], 16;" :: "r"(s), "l"(gsrc));
}
#define CP_COMMIT()  asm volatile("cp.async.commit_group;" ::: "memory")
#define CP_WAIT(N)   asm volatile("cp.async.wait_group %0;" :: "n"(N) : "memory")

// ---------------- prep: pack X into A-frag fp16 ------------------------------
__global__ void cvt_x(const float* __restrict__ x) {
    int idx = blockIdx.x * 256 + threadIdx.x;
    int lane = idx & 31, m16 = (idx >> 5) & 7, kk = (idx >> 8) & 63, mtile = idx >> 14;
    int g = lane >> 2, t = lane & 3;
    const float* p0 = x + (size_t)(mtile * 128 + m16 * 16 + g) * C + kk * 16 + 2 * t;
    const float* p1 = p0 + 8 * C;
    float2 v00 = *(const float2*)p0;
    float2 v10 = *(const float2*)p1;
    float2 v01 = *(const float2*)(p0 + 8);
    float2 v11 = *(const float2*)(p1 + 8);
    g_x[idx] = make_uint4(h2(v00.x, v00.y), h2(v10.x, v10.y),
                          h2(v01.x, v01.y), h2(v11.x, v11.y));
}

// ---------------- prep: pack all 4 W into B-frag fp16 (one launch) -----------
__global__ void wtr_all(const float* __restrict__ wq, const float* __restrict__ wk,
                        const float* __restrict__ wv, const float* __restrict__ wp)
{
    int sel = blockIdx.x >> 10;
    const float* w = (sel == 0) ? wq : (sel == 1) ? wk : (sel == 2) ? wv : wp;
    uint2* dst = (sel == 0) ? g_wq : (sel == 1) ? g_wk : (sel == 2) ? g_wv : g_wp;
    int idx = (blockIdx.x & 1023) * 256 + threadIdx.x;
    int lane = idx & 31, n8 = (idx >> 5) & 15, kk = (idx >> 9) & 63, ntile = idx >> 15;
    int g = lane >> 2, t = lane & 3;
    int n = ntile * 128 + n8 * 8 + g;
    const float* p = w + (size_t)(kk * 16 + 2 * t) * C + n;
    dst[idx] = make_uint2(h2(p[0], p[C]), h2(p[8 * C], p[9 * C]));
}

// ---------------- GEMM: fp16 k16, BK=64, 3-stage cp.async ring ---------------
// 256 thr, 8 warps, warp tile 64x32, block 128x128. Stage 32 KB.
#define GSTG 32768
#define GEMM_SMEM (3 * GSTG)   // 98304 B

template<int QKV>
__global__ __launch_bounds__(256, 2)
void gemm_tc(const float* __restrict__ b0p,
             const float* __restrict__ b1p,
             const float* __restrict__ b2p,
             float* __restrict__ outp)
{
    extern __shared__ char smb[];

    const uint4* Apk;
    const uint2* Bpk;
    const float* bias;
    int sel, ntile;
    if (QKV) {
        Apk = g_x;
        sel = blockIdx.x >> 3;
        ntile = blockIdx.x & 7;
        Bpk  = (sel == 0) ? g_wq : (sel == 1) ? g_wk : g_wv;
        bias = (sel == 0) ? b0p  : (sel == 1) ? b1p  : b2p;
    } else {
        Apk = g_att;
        sel = 3;
        ntile = blockIdx.x;
        Bpk = g_wp; bias = b0p;
    }
    const int mtile = blockIdx.y;
    const int tileM = mtile * 128;
    const int tileN = ntile * 128;

    const int tid   = threadIdx.x;
    const int lane  = tid & 31;
    const int warp  = tid >> 5;
    const int warpM = warp >> 2;     // 0..1
    const int warpN = warp & 3;      // 0..3
    const int g     = lane >> 2;
    const int t     = lane & 3;

    float4 acc[4][4];
    #pragma unroll
    for (int i = 0; i < 4; i++)
        #pragma unroll
        for (int j = 0; j < 4; j++)
            acc[i][j] = make_float4(0.f, 0.f, 0.f, 0.f);

    auto pref = [&](int s, int j) {
        char* As = smb + s * GSTG;            // 16 KB A (1024 uint4)
        char* Bs = As + 16384;                // 16 KB B (2048 uint2)
        const char* ap = (const char*)(Apk + ((size_t)mtile * 64 + 4 * j) * 256);
        const char* bp = (const char*)(Bpk + ((size_t)ntile * 64 + 4 * j) * 512);
        #pragma unroll
        for (int i = 0; i < 4; i++) {
            int o = (tid + i * 256) * 16;
            cp16b(As + o, ap + o);
            cp16b(Bs + o, bp + o);
        }
    };

    pref(0, 0); CP_COMMIT();
    pref(1, 1); CP_COMMIT();

    for (int j = 0; j < 16; j++) {
        if (j < 15) { CP_WAIT(1); } else { CP_WAIT(0); }
        __syncthreads();
        if (j + 2 < 16) { pref((j + 2) % 3, j + 2); CP_COMMIT(); }

        const uint4* As4 = (const uint4*)(smb + (j % 3) * GSTG);
        const uint2* Bs2 = (const uint2*)(smb + (j % 3) * GSTG + 16384);

        #pragma unroll
        for (int kk2 = 0; kk2 < 4; kk2++) {
            uint4 af[4];
            uint2 bf[4];
            #pragma unroll
            for (int mf = 0; mf < 4; mf++)
                af[mf] = As4[(kk2 * 8 + warpM * 4 + mf) * 32 + lane];
            #pragma unroll
            for (int nf = 0; nf < 4; nf++)
                bf[nf] = Bs2[(kk2 * 16 + warpN * 4 + nf) * 32 + lane];
            #pragma unroll
            for (int mf = 0; mf < 4; mf++)
                #pragma unroll
                for (int nf = 0; nf < 4; nf++)
                    mma_f16(acc[mf][nf], af[mf].x, af[mf].y, af[mf].z, af[mf].w,
                            bf[nf].x, bf[nf].y);
        }
    }

    // epilogue
    #pragma unroll
    for (int nf = 0; nf < 4; nf++) {
        const int n0 = tileN + warpN * 32 + nf * 8 + t * 2;
        const float bv0 = bias[n0];
        const float bv1 = bias[n0 + 1];
        float inv = 0.f;
        if (QKV) {
            const int ip = (n0 & 63) >> 1;
            inv = powf(10000.0f, -(float)ip / 32.0f);
        }
        #pragma unroll
        for (int mf = 0; mf < 4; mf++) {
            float4 a = acc[mf][nf];
            const int r0 = tileM + warpM * 64 + mf * 16 + g;
            float x0 = a.x + bv0, x1 = a.y + bv1;
            float y0 = a.z + bv0, y1 = a.w + bv1;
            if (!QKV) {
                *(float2*)&outp[(size_t)r0 * C + n0]       = make_float2(x0, x1);
                *(float2*)&outp[(size_t)(r0 + 8) * C + n0] = make_float2(y0, y1);
            } else {
                const int bb = r0 / T;
                const int t0 = r0 % T;
                const int h  = n0 >> 6;
                const int d0 = n0 & 63;
                const int bh = bb * NH + h;
                if (sel < 2) {
                    float sn, cs;
                    sincosf((float)t0 * inv, &sn, &cs);
                    float u0 = x0 * cs - x1 * sn;
                    float u1 = x0 * sn + x1 * cs;
                    x0 = u0; x1 = u1;
                    sincosf((float)(t0 + 8) * inv, &sn, &cs);
                    float w0 = y0 * cs - y1 * sn;
                    float w1 = y0 * sn + y1 * cs;
                    y0 = w0; y1 = w1;
                }
                if (sel == 0) {
                    float* dst = g_q + (((size_t)bh) * T + t0) * HS + d0;
                    *(float2*)dst            = make_float2(x0, x1);
                    *(float2*)(dst + 8 * HS) = make_float2(y0, y1);
                } else if (sel == 1) {
                    // K packed B-frag: n=key, k=dim
                    const int ktile = t0 >> 6;
                    const int kk  = d0 >> 4;
                    const int c   = d0 & 15;
                    const int tt  = (c & 7) >> 1;
                    const int hf  = c >> 3;
                    uint32_t* kp32 = (uint32_t*)g_kp;
                    size_t idx0 = ((((size_t)bh * 32 + ktile) * 4 + kk) * 256
                                  + ((size_t)((t0 >> 3) & 7)) * 32 + (t0 & 7) * 4 + tt);
                    kp32[idx0 * 2 + hf]        = h2(x0, x1);   // key t0
                    kp32[(idx0 + 32) * 2 + hf] = h2(y0, y1);   // key t0+8
                } else {
                    // V packed B-frag: n=dim, k=key. t0&15 = g (<8) by construction.
                    const int vtile = t0 >> 6;
                    const int kkv = (t0 & 63) >> 4;
                    const int gk  = t0 & 7;
                    const int ttv = gk >> 1;
                    const int kp  = gk & 1;
                    __half* vph = (__half*)g_vp;
                    size_t base = (((size_t)bh * 32 + vtile) * 4 + kkv) * 256;
                    size_t i_x0 = base + (size_t)(d0 >> 3) * 32 + (d0 & 7) * 4 + ttv;
                    size_t i_x1 = base + (size_t)((d0 + 1) >> 3) * 32 + ((d0 + 1) & 7) * 4 + ttv;
                    vph[i_x0 * 4 + kp]     = __float2half_rn(x0);   // key t0,   dim d0
                    vph[i_x1 * 4 + kp]     = __float2half_rn(x1);   // key t0,   dim d0+1
                    vph[i_x0 * 4 + 2 + kp] = __float2half_rn(y0);   // key t0+8, dim d0
                    vph[i_x1 * 4 + 2 + kp] = __float2half_rn(y1);   // key t0+8, dim d0+1
                }
            }
        }
    }
}

// ---------------- flash attention: packed K/V frags, log2-domain softmax -----
// 128 q rows/block, 4 warps, 32 rows/warp. K/V tiles 64 keys, stage = 16 KB.
#define ASTG 16384
#define ATTN_SMEM (3 * ASTG)   // 49152 B

__global__ __launch_bounds__(128, 2)
void attn_tc()
{
    extern __shared__ char smb[];

    const int qt   = gridDim.x - 1 - blockIdx.x;   // big tiles first
    const int h    = blockIdx.y;
    const int bb   = blockIdx.z;
    const int tid  = threadIdx.x;
    const int lane = tid & 31;
    const int warp = tid >> 5;
    const int g    = lane >> 2;
    const int t    = lane & 3;
    const int bh   = bb * NH + h;

    const float* qbase = g_q + ((size_t)bh * T + (size_t)qt * 128) * HS;

    // Q fragments pre-scaled by (1/8)*log2(e) -> scores in log2 domain
    const float SC = 0.125f * 1.44269504088896f;
    uint32_t qa[2][4][4];
    #pragma unroll
    for (int a = 0; a < 2; a++) {
        const int base = warp * 32 + a * 16;
        const float* q0 = qbase + (size_t)(base + g) * HS;
        const float* q1 = q0 + 8 * HS;
        #pragma unroll
        for (int kk = 0; kk < 4; kk++) {
            float2 v00 = *(const float2*)&q0[kk * 16 + 2 * t];
            float2 v10 = *(const float2*)&q1[kk * 16 + 2 * t];
            float2 v01 = *(const float2*)&q0[kk * 16 + 8 + 2 * t];
            float2 v11 = *(const float2*)&q1[kk * 16 + 8 + 2 * t];
            qa[a][kk][0] = h2(v00.x * SC, v00.y * SC);
            qa[a][kk][1] = h2(v10.x * SC, v10.y * SC);
            qa[a][kk][2] = h2(v01.x * SC, v01.y * SC);
            qa[a][kk][3] = h2(v11.x * SC, v11.y * SC);
        }
    }

    auto pref = [&](int s, int kt) {
        char* Kh = smb + s * ASTG;
        char* Vv = Kh + 8192;
        const char* kp = (const char*)(g_kp + ((size_t)bh * 32 + kt) * 1024);
        const char* vp = (const char*)(g_vp + ((size_t)bh * 32 + kt) * 1024);
        #pragma unroll
        for (int i = 0; i < 4; i++) {
            int o = (tid + i * 128) * 16;
            cp16b(Kh + o, kp + o);
            cp16b(Vv + o, vp + o);
        }
    };

    float4 O[2][8];
    float  m[2][2], l[2][2];
    #pragma unroll
    for (int a = 0; a < 2; a++) {
        #pragma unroll
        for (int i = 0; i < 8; i++) O[a][i] = make_float4(0.f, 0.f, 0.f, 0.f);
        m[a][0] = m[a][1] = -1e30f;
        l[a][0] = l[a][1] = 0.f;
    }

    const int ktmax = qt * 2 + 1;

    pref(0, 0); CP_COMMIT();
    pref(1, 1); CP_COMMIT();

    for (int kt = 0; kt <= ktmax; kt++) {
        if (kt < ktmax) { CP_WAIT(1); } else { CP_WAIT(0); }
        __syncthreads();
        if (kt + 2 <= ktmax) { pref((kt + 2) % 3, kt + 2); CP_COMMIT(); }

        const int base0 = qt * 128 + warp * 32;
        const bool act0 = (kt * 64 <= base0 + 15);
        const bool act1 = (kt * 64 <= base0 + 31);
        if (!act1) continue;

        const uint2* Ksm = (const uint2*)(smb + (kt % 3) * ASTG);
        const uint2* Vsm = (const uint2*)(smb + (kt % 3) * ASTG + 8192);

        // --- scores (log2 domain) ---
        float4 S[2][8];
        #pragma unroll
        for (int a = 0; a < 2; a++)
            #pragma unroll
            for (int i = 0; i < 8; i++) S[a][i] = make_float4(0.f, 0.f, 0.f, 0.f);

        #pragma unroll
        for (int kk = 0; kk < 4; kk++) {
            #pragma unroll
            for (int n8 = 0; n8 < 8; n8++) {
                uint2 b = Ksm[(kk * 8 + n8) * 32 + lane];
                if (act0)
                    mma_f16(S[0][n8], qa[0][kk][0], qa[0][kk][1], qa[0][kk][2], qa[0][kk][3], b.x, b.y);
                mma_f16(S[1][n8], qa[1][kk][0], qa[1][kk][1], qa[1][kk][2], qa[1][kk][3], b.x, b.y);
            }
        }

        // --- causal mask ---
        #pragma unroll
        for (int a = 0; a < 2; a++) {
            if (a == 0 && !act0) continue;
            const int base = base0 + a * 16;
            if (kt * 64 + 63 > base) {
                const int r0 = base + g;
                #pragma unroll
                for (int n8 = 0; n8 < 8; n8++) {
                    int c0 = kt * 64 + n8 * 8 + 2 * t;
                    if (c0     > r0    ) S[a][n8].x = -1e30f;
                    if (c0 + 1 > r0    ) S[a][n8].y = -1e30f;
                    if (c0     > r0 + 8) S[a][n8].z = -1e30f;
                    if (c0 + 1 > r0 + 8) S[a][n8].w = -1e30f;
                }
            }
        }

        // --- online softmax (exp2) ---
        #pragma unroll
        for (int a = 0; a < 2; a++) {
            if (a == 0 && !act0) continue;
            float mx0 = -1e30f, mx1 = -1e30f;
            #pragma unroll
            for (int n8 = 0; n8 < 8; n8++) {
                mx0 = fmaxf(mx0, fmaxf(S[a][n8].x, S[a][n8].y));
                mx1 = fmaxf(mx1, fmaxf(S[a][n8].z, S[a][n8].w));
            }
            mx0 = fmaxf(mx0, __shfl_xor_sync(0xffffffffu, mx0, 1));
            mx0 = fmaxf(mx0, __shfl_xor_sync(0xffffffffu, mx0, 2));
            mx1 = fmaxf(mx1, __shfl_xor_sync(0xffffffffu, mx1, 1));
            mx1 = fmaxf(mx1, __shfl_xor_sync(0xffffffffu, mx1, 2));

            float nm0 = fmaxf(m[a][0], mx0);
            float nm1 = fmaxf(m[a][1], mx1);
            float c0 = exp2f(m[a][0] - nm0);
            float c1 = exp2f(m[a][1] - nm1);
            m[a][0] = nm0; m[a][1] = nm1;
            l[a][0] *= c0; l[a][1] *= c1;

            #pragma unroll
            for (int n8 = 0; n8 < 8; n8++) {
                S[a][n8].x = exp2f(S[a][n8].x - nm0);
                S[a][n8].y = exp2f(S[a][n8].y - nm0);
                S[a][n8].z = exp2f(S[a][n8].z - nm1);
                S[a][n8].w = exp2f(S[a][n8].w - nm1);
                l[a][0] += S[a][n8].x + S[a][n8].y;
                l[a][1] += S[a][n8].z + S[a][n8].w;
                O[a][n8].x *= c0; O[a][n8].y *= c0;
                O[a][n8].z *= c1; O[a][n8].w *= c1;
            }
        }

        // --- O += P V : C-frag -> A-frag identity ---
        #pragma unroll
        for (int kk = 0; kk < 4; kk++) {
            uint32_t pa[2][4];
            #pragma unroll
            for (int a = 0; a < 2; a++) {
                if (a == 0 && !act0) continue;
                pa[a][0] = h2(S[a][2 * kk].x,     S[a][2 * kk].y);
                pa[a][1] = h2(S[a][2 * kk].z,     S[a][2 * kk].w);
                pa[a][2] = h2(S[a][2 * kk + 1].x, S[a][2 * kk + 1].y);
                pa[a][3] = h2(S[a][2 * kk + 1].z, S[a][2 * kk + 1].w);
            }
            #pragma unroll
            for (int n8 = 0; n8 < 8; n8++) {
                uint2 b = Vsm[(kk * 8 + n8) * 32 + lane];
                if (act0)
                    mma_f16(O[0][n8], pa[0][0], pa[0][1], pa[0][2], pa[0][3], b.x, b.y);
                mma_f16(O[1][n8], pa[1][0], pa[1][1], pa[1][2], pa[1][3], b.x, b.y);
            }
        }
    }

    // normalize + store into A-packed fp16 g_att for the proj GEMM
    #pragma unroll
    for (int a = 0; a < 2; a++) {
        float l0 = l[a][0], l1 = l[a][1];
        l0 += __shfl_xor_sync(0xffffffffu, l0, 1);
        l0 += __shfl_xor_sync(0xffffffffu, l0, 2);
        l1 += __shfl_xor_sync(0xffffffffu, l1, 1);
        l1 += __shfl_xor_sync(0xffffffffu, l1, 2);
        const float i0 = 1.0f / l0;
        const float i1 = 1.0f / l1;

        const int mtile = bb * 16 + qt;
        const int m16   = warp * 2 + a;
        #pragma unroll
        for (int kk = 0; kk < 4; kk++) {
            uint4 u;
            u.x = h2(O[a][2 * kk].x * i0,     O[a][2 * kk].y * i0);
            u.y = h2(O[a][2 * kk].z * i1,     O[a][2 * kk].w * i1);
            u.z = h2(O[a][2 * kk + 1].x * i0, O[a][2 * kk + 1].y * i0);
            u.w = h2(O[a][2 * kk + 1].z * i1, O[a][2 * kk + 1].w * i1);
            g_att[(((size_t)mtile * 64 + h * 4 + kk) * 8 + m16) * 32 + lane] = u;
        }
    }
}

// ---------------------------------------------------------------------------
extern "C" void kernel_launch(void* const* d_in, const int* in_sizes, int n_in,
                              void* d_out, int out_size)
{
    const float* x  = (const float*)d_in[0];
    const float* Wq = (const float*)d_in[1];
    const float* bq = (const float*)d_in[2];
    const float* Wk = (const float*)d_in[3];
    const float* bk = (const float*)d_in[4];
    const float* Wv = (const float*)d_in[5];
    const float* bv = (const float*)d_in[6];
    const float* Wp = (const float*)d_in[7];
    const float* bp = (const float*)d_in[8];
    float* out = (float*)d_out;

    cudaFuncSetAttribute(gemm_tc<1>, cudaFuncAttributeMaxDynamicSharedMemorySize, GEMM_SMEM);
    cudaFuncSetAttribute(gemm_tc<0>, cudaFuncAttributeMaxDynamicSharedMemorySize, GEMM_SMEM);
    cudaFuncSetAttribute(attn_tc,    cudaFuncAttributeMaxDynamicSharedMemorySize, ATTN_SMEM);

    // prep: pack X (A-frag) and all W's (B-frag) in fp16
    cvt_x<<<4096, 256>>>(x);
    wtr_all<<<4096, 256>>>(Wq, Wk, Wv, Wp);

    dim3 gq(24, M / 128);   // fused QKV
    gemm_tc<1><<<gq, 256, GEMM_SMEM>>>(bq, bk, bv, nullptr);

    dim3 ga(T / 128, NH, Bz);
    attn_tc<<<ga, 128, ATTN_SMEM>>>();

    dim3 gp(8, M / 128);
    gemm_tc<0><<<gp, 256, GEMM_SMEM>>>(bp, nullptr, nullptr, out);
}